// round 13
// baseline (speedup 1.0000x reference)
#include <cuda_runtime.h>
#include <cuda_bf16.h>
#include <cstdint>

// Batched Newton-Schulz matrix sqrt: 1024 x (128x128 fp32), 5 iterations.
// mma.sync bf16 + ldmatrix, fp32 via hi+lo split (hh+hl+lh), triangular
// outputs + mirror. P2 uses m64n32 column-panel tasks (128 B/MMA) with a
// B-resident / A-streaming loop that keeps registers ~105.

#define NMAT 128
#define NT 512
#define PITCH32 68      // u32 words per smem row
#define PITCHB 272      // bytes per smem row
#define PITCH16 136

__device__ __forceinline__ void mma16816(float* d, const uint32_t* a,
                                         const uint32_t* b) {
    asm volatile(
        "mma.sync.aligned.m16n8k16.row.col.f32.bf16.bf16.f32 "
        "{%0,%1,%2,%3}, {%4,%5,%6,%7}, {%8,%9}, {%0,%1,%2,%3};"
        : "+f"(d[0]), "+f"(d[1]), "+f"(d[2]), "+f"(d[3])
        : "r"(a[0]), "r"(a[1]), "r"(a[2]), "r"(a[3]), "r"(b[0]), "r"(b[1]));
}

#define LDSM4(r_, a_)                                                         \
    asm volatile("ldmatrix.sync.aligned.m8n8.x4.shared.b16 {%0,%1,%2,%3}, [%4];" \
                 : "=r"((r_)[0]), "=r"((r_)[1]), "=r"((r_)[2]), "=r"((r_)[3])  \
                 : "r"(a_))

__device__ __forceinline__ uint32_t sp(const void* p) {
    return (uint32_t)__cvta_generic_to_shared(p);
}

__device__ __forceinline__ void split2f(float v0, float v1, uint32_t& hw,
                                        uint32_t& lw) {
    asm("cvt.rn.bf16x2.f32 %0, %1, %2;" : "=r"(hw) : "f"(v1), "f"(v0));
    float h0 = __uint_as_float(hw << 16);
    float h1 = __uint_as_float(hw & 0xffff0000u);
    float l0 = v0 - h0, l1 = v1 - h1;
    asm("cvt.rn.bf16x2.f32 %0, %1, %2;" : "=r"(lw) : "f"(l1), "f"(l0));
}

__device__ __forceinline__ void zero4(float a[4][4]) {
#pragma unroll
    for (int i = 0; i < 4; i++)
#pragma unroll
        for (int j = 0; j < 4; j++) a[i][j] = 0.f;
}

// ldmatrix octet addressing
__device__ __forceinline__ uint32_t a_off(int r0, int lane) {
    return (uint32_t)((r0 + (lane & 7) + ((lane >> 3) & 1) * 8) * PITCHB +
                      (lane >> 4) * 16);
}
__device__ __forceinline__ uint32_t b_off(int c0, int lane) {
    return (uint32_t)((c0 + (lane & 7) + (lane >> 4) * 8) * PITCHB +
                      ((lane >> 3) & 1) * 16);
}

// m16n32 single product (double-buffered): acc += Ph@Qh + Ph@Ql + Pl@Qh
__device__ __forceinline__ void mm_half(const uint32_t* Ph, const uint32_t* Pl,
                                        const uint32_t* Qh, const uint32_t* Ql,
                                        float acc[4][4], int r0, int c0,
                                        int lane) {
    const uint32_t ao = a_off(r0, lane), bo = b_off(c0, lane);
    uint32_t pah = sp(Ph) + ao, pal = sp(Pl) + ao;
    uint32_t qh0 = sp(Qh) + bo, qh1 = qh0 + 16 * PITCHB;
    uint32_t ql0 = sp(Ql) + bo, ql1 = ql0 + 16 * PITCHB;
    uint32_t ah[2][4], al[2][4], bh[2][8], bl[2][8];
    LDSM4(ah[0], pah); LDSM4(al[0], pal);
    LDSM4(bh[0], qh0); LDSM4(bh[0] + 4, qh1);
    LDSM4(bl[0], ql0); LDSM4(bl[0] + 4, ql1);
#pragma unroll
    for (int k = 0; k < 8; k++) {
        const int c = k & 1, n = c ^ 1;
        if (k < 7) {
            pah += 32; pal += 32; qh0 += 32; qh1 += 32; ql0 += 32; ql1 += 32;
            LDSM4(ah[n], pah); LDSM4(al[n], pal);
            LDSM4(bh[n], qh0); LDSM4(bh[n] + 4, qh1);
            LDSM4(bl[n], ql0); LDSM4(bl[n] + 4, ql1);
        }
#pragma unroll
        for (int ni = 0; ni < 4; ni++) {
            mma16816(acc[ni], ah[c], bh[c] + ni * 2);
            mma16816(acc[ni], ah[c], bl[c] + ni * 2);
            mma16816(acc[ni], al[c], bh[c] + ni * 2);
        }
    }
}

// m32n32 single product (B amortized over 32 rows, single-buffered)
__device__ __forceinline__ void mm32(const uint32_t* Ph, const uint32_t* Pl,
                                     const uint32_t* Qh, const uint32_t* Ql,
                                     float acc[2][4][4], int r0, int c0,
                                     int lane) {
    const uint32_t ao0 = a_off(r0, lane), ao1 = a_off(r0 + 16, lane);
    const uint32_t bo = b_off(c0, lane);
    uint32_t ph0 = sp(Ph) + ao0, ph1 = sp(Ph) + ao1;
    uint32_t pl0 = sp(Pl) + ao0, pl1 = sp(Pl) + ao1;
    uint32_t qh0 = sp(Qh) + bo, qh1 = qh0 + 16 * PITCHB;
    uint32_t ql0 = sp(Ql) + bo, ql1 = ql0 + 16 * PITCHB;
#pragma unroll
    for (int k = 0; k < 8; k++) {
        uint32_t ah[2][4], al[2][4], bh[8], bl[8];
        LDSM4(ah[0], ph0); LDSM4(ah[1], ph1);
        LDSM4(al[0], pl0); LDSM4(al[1], pl1);
        LDSM4(bh, qh0); LDSM4(bh + 4, qh1);
        LDSM4(bl, ql0); LDSM4(bl + 4, ql1);
        ph0 += 32; ph1 += 32; pl0 += 32; pl1 += 32;
        qh0 += 32; qh1 += 32; ql0 += 32; ql1 += 32;
#pragma unroll
        for (int ni = 0; ni < 4; ni++) {
            mma16816(acc[0][ni], ah[0], bh + ni * 2);
            mma16816(acc[1][ni], ah[1], bh + ni * 2);
            mma16816(acc[0][ni], ah[0], bl + ni * 2);
            mma16816(acc[1][ni], ah[1], bl + ni * 2);
            mma16816(acc[0][ni], al[0], bh + ni * 2);
            mma16816(acc[1][ni], al[1], bh + ni * 2);
        }
    }
}

// m64n32 single product: B resident (16 regs), A streamed per row-group.
__device__ __forceinline__ void mm64(const uint32_t* Ph, const uint32_t* Pl,
                                     const uint32_t* Qh, const uint32_t* Ql,
                                     float acc[4][4][4], int r0, int c0,
                                     int lane) {
    const uint32_t bo = b_off(c0, lane);
    uint32_t qh0 = sp(Qh) + bo, qh1 = qh0 + 16 * PITCHB;
    uint32_t ql0 = sp(Ql) + bo, ql1 = ql0 + 16 * PITCHB;
    const uint32_t ao = a_off(r0, lane);
    const uint32_t pah = sp(Ph) + ao, pal = sp(Pl) + ao;
#pragma unroll
    for (int k = 0; k < 8; k++) {
        uint32_t bh[8], bl[8];
        LDSM4(bh, qh0); LDSM4(bh + 4, qh1);
        LDSM4(bl, ql0); LDSM4(bl + 4, ql1);
        qh0 += 32; qh1 += 32; ql0 += 32; ql1 += 32;
#pragma unroll
        for (int mi = 0; mi < 4; mi++) {
            uint32_t ah[4], al[4];
            const uint32_t aoff = (uint32_t)(mi * 16 * PITCHB + k * 32);
            LDSM4(ah, pah + aoff);
            LDSM4(al, pal + aoff);
#pragma unroll
            for (int ni = 0; ni < 4; ni++) {
                mma16816(acc[mi][ni], ah, bh + ni * 2);
                mma16816(acc[mi][ni], ah, bl + ni * 2);
                mma16816(acc[mi][ni], al, bh + ni * 2);
            }
        }
    }
}

// v = alpha*acc + beta*I -> hi/lo pair; optional mirror to transposed pos.
__device__ __forceinline__ void epi_half(const float acc[4][4],
                                         uint32_t* __restrict__ Bh,
                                         uint32_t* __restrict__ Bl, float alpha,
                                         float beta, int r0, int c0, int lane,
                                         bool mir) {
    const int qr = lane >> 2, cp = (lane & 3) * 2;
    uint16_t* H16 = (uint16_t*)Bh;
    uint16_t* L16 = (uint16_t*)Bl;
#pragma unroll
    for (int ni = 0; ni < 4; ni++) {
        const int col = c0 + ni * 8 + cp;
#pragma unroll
        for (int h = 0; h < 2; h++) {
            const int row = r0 + qr + h * 8;
            float v0 = alpha * acc[ni][2 * h]     + ((row == col)     ? beta : 0.f);
            float v1 = alpha * acc[ni][2 * h + 1] + ((row == col + 1) ? beta : 0.f);
            uint32_t hw, lw;
            split2f(v0, v1, hw, lw);
            const int idx = row * PITCH32 + (col >> 1);
            Bh[idx] = hw;
            Bl[idx] = lw;
            if (mir) {
                H16[col * PITCH16 + row]       = (uint16_t)hw;
                H16[(col + 1) * PITCH16 + row] = (uint16_t)(hw >> 16);
                L16[col * PITCH16 + row]       = (uint16_t)lw;
                L16[(col + 1) * PITCH16 + row] = (uint16_t)(lw >> 16);
            }
        }
    }
}

__device__ __forceinline__ void epi_out_half(const float acc[4][4],
                                             float* __restrict__ Ob, float s,
                                             int r0, int c0, int lane) {
    const int qr = lane >> 2, cp = (lane & 3) * 2;
#pragma unroll
    for (int ni = 0; ni < 4; ni++) {
        const int col = c0 + ni * 8 + cp;
#pragma unroll
        for (int h = 0; h < 2; h++) {
            const int row = r0 + qr + h * 8;
            *(float2*)(Ob + row * 128 + col) =
                make_float2(s * acc[ni][2 * h], s * acc[ni][2 * h + 1]);
        }
    }
}

__device__ __constant__ int LTI[10] = {0, 1, 1, 2, 2, 2, 3, 3, 3, 3};
__device__ __constant__ int LTJ[10] = {0, 0, 1, 0, 1, 2, 0, 1, 2, 3};
// P2 m64 column-panels (rows r..r+63 x cols c..c+31 of lower triangle)
__device__ __constant__ int P64R[4] = {0, 64, 32, 64};
__device__ __constant__ int P64C[4] = {0, 0, 32, 64};

__global__ void __launch_bounds__(NT, 1)
ns_p64_kernel(const float* __restrict__ A, float* __restrict__ Out) {
    extern __shared__ uint32_t sm[];
    uint32_t* Yh = sm;
    uint32_t* Yl = sm + 128 * PITCH32;
    uint32_t* Zh = sm + 2 * 128 * PITCH32;
    uint32_t* Zl = sm + 3 * 128 * PITCH32;
    uint32_t* Th = sm + 4 * 128 * PITCH32;
    uint32_t* Tl = sm + 5 * 128 * PITCH32;
    __shared__ float red[16];

    const int tid = threadIdx.x, w = tid >> 5, lane = tid & 31;
    const float* Ab = A + (size_t)blockIdx.x * 16384;
    float* Ob = Out + (size_t)blockIdx.x * 16384;

    // --- P1 / iter1 geometry (as R12) ---
    const bool pbig = (w < 8);
    const bool p1act = (w < 12);
    const int p1t = pbig ? w : (8 + ((w - 8) >> 1));
    const int P1r = LTI[p1t] * 32 + (pbig ? 0 : ((w - 8) & 1) * 16);
    const int P1c = LTJ[p1t] * 32;
    const bool P1m = (LTI[p1t] != LTJ[p1t]);
    // --- P2 geometry: 8 m64 panels (warps 0-7) + 4 m32 panels (8-11) ---
    const bool p2m64 = (w < 8);
    const bool p2m32 = (w >= 8) && (w < 12);
    const bool p2z = p2m64 ? (w >= 4) : (w >= 10);
    const int p2i = w & 3;
    const int P2r = p2m64 ? P64R[p2i] : 96;
    const int P2c = p2m64 ? P64C[p2i] : ((w & 1) ? 96 : 32);
    // --- last iter: 16 full m32 tiles, warp w -> tile w ---
    const int Lr = (w & 3) * 32, Lc = (w >> 2) * 32;

    // ---- Frobenius norm ----
    float ss = 0.f;
    const float4* A4 = (const float4*)Ab;
    for (int i = tid; i < 4096; i += NT) {
        float4 v = A4[i];
        ss = fmaf(v.x, v.x, fmaf(v.y, v.y, fmaf(v.z, v.z, fmaf(v.w, v.w, ss))));
    }
#pragma unroll
    for (int o = 16; o; o >>= 1) ss += __shfl_xor_sync(0xffffffffu, ss, o);
    if (lane == 0) red[w] = ss;
    __syncthreads();
    float tot = 0.f;
#pragma unroll
    for (int i = 0; i < 16; i++) tot += red[i];
    const float normA = sqrtf(tot);
    const float inv = 1.f / normA;

    // ---- Init: Y0 = A*inv; T1 = Z1 = 1.5I - 0.5*Y0 (all split) ----
    for (int u = tid; u < 2048; u += NT) {
        const int row = u >> 4;
        const int col = (u & 15) * 8;
        float4 a0 = *(const float4*)(Ab + row * 128 + col);
        float4 a1 = *(const float4*)(Ab + row * 128 + col + 4);
        float yv[8] = {a0.x * inv, a0.y * inv, a0.z * inv, a0.w * inv,
                       a1.x * inv, a1.y * inv, a1.z * inv, a1.w * inv};
#pragma unroll
        for (int jj = 0; jj < 4; jj++) {
            const int cc = col + 2 * jj;
            const int idx = row * PITCH32 + (cc >> 1);
            uint32_t hw, lw;
            split2f(yv[2 * jj], yv[2 * jj + 1], hw, lw);
            Yh[idx] = hw; Yl[idx] = lw;
            float q0 = -0.5f * yv[2 * jj]     + (row == cc     ? 1.5f : 0.f);
            float q1 = -0.5f * yv[2 * jj + 1] + (row == cc + 1 ? 1.5f : 0.f);
            split2f(q0, q1, hw, lw);
            Th[idx] = hw; Tl[idx] = lw;
            Zh[idx] = hw; Zl[idx] = lw;
        }
    }
    __syncthreads();

    // ---- iter 1 (reduced): Y = Y @ T1, triangular ----
    {
        float acc[2][4][4];
        zero4(acc[0]); zero4(acc[1]);
        if (pbig)       mm32(Yh, Yl, Th, Tl, acc, P1r, P1c, lane);
        else if (p1act) mm_half(Yh, Yl, Th, Tl, acc[0], P1r, P1c, lane);
        __syncthreads();
        if (p1act) {
            epi_half(acc[0], Yh, Yl, 1.f, 0.f, P1r, P1c, lane, P1m);
            if (pbig)
                epi_half(acc[1], Yh, Yl, 1.f, 0.f, P1r + 16, P1c, lane, P1m);
        }
        __syncthreads();
    }

    // ---- iters 2..5 ----
#pragma unroll 1
    for (int it = 1; it < 5; ++it) {
        // P1: T = 1.5I - 0.5*(Z @ Y); epilogue fused (T not a P1 operand)
        {
            float acc[2][4][4];
            zero4(acc[0]); zero4(acc[1]);
            if (pbig) {
                mm32(Zh, Zl, Yh, Yl, acc, P1r, P1c, lane);
                epi_half(acc[0], Th, Tl, -0.5f, 1.5f, P1r, P1c, lane, P1m);
                epi_half(acc[1], Th, Tl, -0.5f, 1.5f, P1r + 16, P1c, lane, P1m);
            } else if (p1act) {
                mm_half(Zh, Zl, Yh, Yl, acc[0], P1r, P1c, lane);
                epi_half(acc[0], Th, Tl, -0.5f, 1.5f, P1r, P1c, lane, P1m);
            }
        }
        __syncthreads();

        if (it < 4) {
            // P2: Y = Y@T / Z = Z@T via m64 column-panels + m32 tails
            float acc[4][4][4];
            if (p2m64) {
                zero4(acc[0]); zero4(acc[1]); zero4(acc[2]); zero4(acc[3]);
                if (p2z) mm64(Zh, Zl, Th, Tl, acc, P2r, P2c, lane);
                else     mm64(Yh, Yl, Th, Tl, acc, P2r, P2c, lane);
            } else if (p2m32) {
                zero4(acc[0]); zero4(acc[1]);
                if (p2z) mm32(Zh, Zl, Th, Tl, (float(*)[4][4])acc, P2r, P2c, lane);
                else     mm32(Yh, Yl, Th, Tl, (float(*)[4][4])acc, P2r, P2c, lane);
            }
            __syncthreads();
            uint32_t* Dh = p2z ? Zh : Yh;
            uint32_t* Dl = p2z ? Zl : Yl;
            if (p2m64) {
#pragma unroll
                for (int g = 0; g < 4; g++) {
                    const int rg = P2r + g * 16;
                    epi_half(acc[g], Dh, Dl, 1.f, 0.f, rg, P2c, lane,
                             (rg >> 5) != (P2c >> 5));
                }
            } else if (p2m32) {
#pragma unroll
                for (int g = 0; g < 2; g++) {
                    const int rg = P2r + g * 16;
                    epi_half(acc[g], Dh, Dl, 1.f, 0.f, rg, P2c, lane,
                             (rg >> 5) != (P2c >> 5));
                }
            }
            __syncthreads();
        } else {
            // Last: Y5 = Y@T full grid (16 m32 tiles), straight to GMEM
            const float s = sqrtf(normA);
            float acc[2][4][4];
            zero4(acc[0]); zero4(acc[1]);
            mm32(Yh, Yl, Th, Tl, acc, Lr, Lc, lane);
            epi_out_half(acc[0], Ob, s, Lr, Lc, lane);
            epi_out_half(acc[1], Ob, s, Lr + 16, Lc, lane);
        }
    }
}

extern "C" void kernel_launch(void* const* d_in, const int* in_sizes, int n_in,
                              void* d_out, int out_size) {
    const float* A = (const float*)d_in[0];
    float* out = (float*)d_out;
    const int nbatch = in_sizes[0] / (NMAT * NMAT);            // 1024
    const size_t smem = 6 * 128 * PITCH32 * sizeof(uint32_t);  // 208896 B
    cudaFuncSetAttribute(ns_p64_kernel,
                         cudaFuncAttributeMaxDynamicSharedMemorySize, (int)smem);
    ns_p64_kernel<<<nbatch, NT, smem>>>(A, out);
}

// round 14
// speedup vs baseline: 1.2071x; 1.2071x over previous
#include <cuda_runtime.h>
#include <cuda_bf16.h>
#include <cstdint>

// Batched Newton-Schulz matrix sqrt: 1024 x (128x128 fp32), 5 iterations.
// Single-pass TF32 mma.sync (m16n8k8) + ldmatrix. Operands stored in smem
// as tf32-rounded fp32 (cvt.rna in epilogue) -> products exact in fp32.
// Triangular outputs + mirror (all iterates symmetric & commuting).
// P1: m32 tiles; P2: m64n32 column panels (192 B smem per MMA).

#define NMAT 128
#define NT 512
#define PITCHW 132      // fp32 words per smem row
#define PITCHB 528      // bytes per smem row (16*33: ldmatrix conflict-free)

__device__ __forceinline__ void mma_tf32(float* d, const uint32_t* a,
                                         uint32_t b0, uint32_t b1) {
    asm volatile(
        "mma.sync.aligned.m16n8k8.row.col.f32.tf32.tf32.f32 "
        "{%0,%1,%2,%3}, {%4,%5,%6,%7}, {%8,%9}, {%0,%1,%2,%3};"
        : "+f"(d[0]), "+f"(d[1]), "+f"(d[2]), "+f"(d[3])
        : "r"(a[0]), "r"(a[1]), "r"(a[2]), "r"(a[3]), "r"(b0), "r"(b1));
}

#define LDSM4(r_, a_)                                                         \
    asm volatile("ldmatrix.sync.aligned.m8n8.x4.shared.b16 {%0,%1,%2,%3}, [%4];" \
                 : "=r"((r_)[0]), "=r"((r_)[1]), "=r"((r_)[2]), "=r"((r_)[3])  \
                 : "r"(a_))

__device__ __forceinline__ uint32_t sp(const void* p) {
    return (uint32_t)__cvta_generic_to_shared(p);
}

__device__ __forceinline__ uint32_t tf32r(float x) {
    uint32_t r;
    asm("cvt.rna.tf32.f32 %0, %1;" : "=r"(r) : "f"(x));
    return r;
}

__device__ __forceinline__ void zero4(float a[4][4]) {
#pragma unroll
    for (int i = 0; i < 4; i++)
#pragma unroll
        for (int j = 0; j < 4; j++) a[i][j] = 0.f;
}

// ldmatrix octet addressing (fp32 rows; 16B chunk = 4 fp32 along k)
__device__ __forceinline__ uint32_t a_off(int r0, int lane) {
    return (uint32_t)((r0 + (lane & 7) + ((lane >> 3) & 1) * 8) * PITCHB +
                      (lane >> 4) * 16);
}
__device__ __forceinline__ uint32_t b_off(int c0, int lane) {
    return (uint32_t)((c0 + (lane & 7) + (lane >> 4) * 8) * PITCHB +
                      ((lane >> 3) & 1) * 16);
}

// m16n32: acc[4][4]
__device__ __forceinline__ void mm16(const uint32_t* P, const uint32_t* Q,
                                     float acc[4][4], int r0, int c0, int lane) {
    const uint32_t pa = sp(P) + a_off(r0, lane);
    uint32_t qb0 = sp(Q) + b_off(c0, lane);
    uint32_t qb1 = qb0 + 16 * PITCHB;
#pragma unroll
    for (int k = 0; k < 16; k++) {
        uint32_t a[4], b0[4], b1[4];
        LDSM4(a, pa + k * 32);
        LDSM4(b0, qb0); LDSM4(b1, qb1);
        qb0 += 32; qb1 += 32;
        mma_tf32(acc[0], a, b0[0], b0[1]);
        mma_tf32(acc[1], a, b0[2], b0[3]);
        mma_tf32(acc[2], a, b1[0], b1[1]);
        mma_tf32(acc[3], a, b1[2], b1[3]);
    }
}

// m32n32: acc[2][4][4]
__device__ __forceinline__ void mm32(const uint32_t* P, const uint32_t* Q,
                                     float acc[2][4][4], int r0, int c0,
                                     int lane) {
    const uint32_t pa0 = sp(P) + a_off(r0, lane);
    const uint32_t pa1 = sp(P) + a_off(r0 + 16, lane);
    uint32_t qb0 = sp(Q) + b_off(c0, lane);
    uint32_t qb1 = qb0 + 16 * PITCHB;
#pragma unroll
    for (int k = 0; k < 16; k++) {
        uint32_t a0[4], a1[4], b0[4], b1[4];
        LDSM4(a0, pa0 + k * 32);
        LDSM4(a1, pa1 + k * 32);
        LDSM4(b0, qb0); LDSM4(b1, qb1);
        qb0 += 32; qb1 += 32;
        mma_tf32(acc[0][0], a0, b0[0], b0[1]);
        mma_tf32(acc[1][0], a1, b0[0], b0[1]);
        mma_tf32(acc[0][1], a0, b0[2], b0[3]);
        mma_tf32(acc[1][1], a1, b0[2], b0[3]);
        mma_tf32(acc[0][2], a0, b1[0], b1[1]);
        mma_tf32(acc[1][2], a1, b1[0], b1[1]);
        mma_tf32(acc[0][3], a0, b1[2], b1[3]);
        mma_tf32(acc[1][3], a1, b1[2], b1[3]);
    }
}

// m64n32: acc[4][4][4], B resident per k-step, A streamed per row-group
__device__ __forceinline__ void mm64(const uint32_t* P, const uint32_t* Q,
                                     float acc[4][4][4], int r0, int c0,
                                     int lane) {
    const uint32_t pa = sp(P) + a_off(r0, lane);
    uint32_t qb0 = sp(Q) + b_off(c0, lane);
    uint32_t qb1 = qb0 + 16 * PITCHB;
#pragma unroll
    for (int k = 0; k < 16; k++) {
        uint32_t b0[4], b1[4];
        LDSM4(b0, qb0); LDSM4(b1, qb1);
        qb0 += 32; qb1 += 32;
#pragma unroll
        for (int mi = 0; mi < 4; mi++) {
            uint32_t a[4];
            LDSM4(a, pa + (uint32_t)(mi * 16 * PITCHB + k * 32));
            mma_tf32(acc[mi][0], a, b0[0], b0[1]);
            mma_tf32(acc[mi][1], a, b0[2], b0[3]);
            mma_tf32(acc[mi][2], a, b1[0], b1[1]);
            mma_tf32(acc[mi][3], a, b1[2], b1[3]);
        }
    }
}

// v = alpha*acc + beta*I -> tf32-rounded fp32 words; optional mirror.
__device__ __forceinline__ void epi_t(const float acc[4][4],
                                      uint32_t* __restrict__ B, float alpha,
                                      float beta, int r0, int c0, int lane,
                                      bool mir) {
    const int qr = lane >> 2, cp = (lane & 3) * 2;
#pragma unroll
    for (int ni = 0; ni < 4; ni++) {
        const int col = c0 + ni * 8 + cp;
#pragma unroll
        for (int h = 0; h < 2; h++) {
            const int row = r0 + qr + h * 8;
            float v0 = alpha * acc[ni][2 * h]     + ((row == col)     ? beta : 0.f);
            float v1 = alpha * acc[ni][2 * h + 1] + ((row == col + 1) ? beta : 0.f);
            uint32_t u0 = tf32r(v0), u1 = tf32r(v1);
            *(uint2*)(B + row * PITCHW + col) = make_uint2(u0, u1);
            if (mir) {
                B[col * PITCHW + row] = u0;
                B[(col + 1) * PITCHW + row] = u1;
            }
        }
    }
}

__device__ __forceinline__ void epi_out(const float acc[4][4],
                                        float* __restrict__ Ob, float s,
                                        int r0, int c0, int lane) {
    const int qr = lane >> 2, cp = (lane & 3) * 2;
#pragma unroll
    for (int ni = 0; ni < 4; ni++) {
        const int col = c0 + ni * 8 + cp;
#pragma unroll
        for (int h = 0; h < 2; h++) {
            const int row = r0 + qr + h * 8;
            *(float2*)(Ob + row * 128 + col) =
                make_float2(s * acc[ni][2 * h], s * acc[ni][2 * h + 1]);
        }
    }
}

__device__ __constant__ int LTI[10] = {0, 1, 1, 2, 2, 2, 3, 3, 3, 3};
__device__ __constant__ int LTJ[10] = {0, 0, 1, 0, 1, 2, 0, 1, 2, 3};
// P2 m64 column-panels of the lower triangle
__device__ __constant__ int P64R[4] = {0, 64, 32, 64};
__device__ __constant__ int P64C[4] = {0, 0, 32, 64};

__global__ void __launch_bounds__(NT, 1)
ns_tf32_kernel(const float* __restrict__ A, float* __restrict__ Out) {
    extern __shared__ uint32_t sm[];
    uint32_t* Yb = sm;
    uint32_t* Zb = sm + 128 * PITCHW;
    uint32_t* Tb = sm + 2 * 128 * PITCHW;
    __shared__ float red[16];

    const int tid = threadIdx.x, w = tid >> 5, lane = tid & 31;
    const float* Ab = A + (size_t)blockIdx.x * 16384;
    float* Ob = Out + (size_t)blockIdx.x * 16384;

    // --- P1 geometry: warps 0-7 m32 tiles 0-7; warps 8-11 m16 halves of
    // tiles 8 ((3,2), mirror) and 9 ((3,3), diag) ---
    const bool pbig = (w < 8);
    const bool p1act = (w < 12);
    const int p1t = pbig ? w : (8 + ((w - 8) >> 1));
    const int P1r = LTI[p1t] * 32 + (pbig ? 0 : ((w - 8) & 1) * 16);
    const int P1c = LTJ[p1t] * 32;
    const bool P1m = (LTI[p1t] != LTJ[p1t]);
    // --- P2: 8 m64 panels (warps 0-7) + 4 m32 panels (warps 8-11) ---
    const bool p2m64 = (w < 8);
    const bool p2m32 = (w >= 8) && (w < 12);
    const bool p2z = p2m64 ? (w >= 4) : (w >= 10);
    const int p2i = w & 3;
    const int P2r = p2m64 ? P64R[p2i] : 96;
    const int P2c = p2m64 ? P64C[p2i] : ((w & 1) ? 96 : 32);
    // --- last iter: 16 m32 tiles ---
    const int Lr = (w & 3) * 32, Lc = (w >> 2) * 32;

    // ---- Frobenius norm ----
    float ss = 0.f;
    const float4* A4 = (const float4*)Ab;
    for (int i = tid; i < 4096; i += NT) {
        float4 v = A4[i];
        ss = fmaf(v.x, v.x, fmaf(v.y, v.y, fmaf(v.z, v.z, fmaf(v.w, v.w, ss))));
    }
#pragma unroll
    for (int o = 16; o; o >>= 1) ss += __shfl_xor_sync(0xffffffffu, ss, o);
    if (lane == 0) red[w] = ss;
    __syncthreads();
    float tot = 0.f;
#pragma unroll
    for (int i = 0; i < 16; i++) tot += red[i];
    const float normA = sqrtf(tot);
    const float inv = 1.f / normA;

    // ---- Init: Y0 = tf32(A*inv); T1 = Z1 = tf32(1.5I - 0.5*Y0) ----
    for (int u = tid; u < 2048; u += NT) {
        const int row = u >> 4;
        const int col = (u & 15) * 8;
        float4 a0 = *(const float4*)(Ab + row * 128 + col);
        float4 a1 = *(const float4*)(Ab + row * 128 + col + 4);
        float yv[8] = {a0.x * inv, a0.y * inv, a0.z * inv, a0.w * inv,
                       a1.x * inv, a1.y * inv, a1.z * inv, a1.w * inv};
#pragma unroll
        for (int j = 0; j < 8; j++) {
            const int cc = col + j;
            const int idx = row * PITCHW + cc;
            uint32_t yb = tf32r(yv[j]);
            Yb[idx] = yb;
            float t = -0.5f * yv[j] + (row == cc ? 1.5f : 0.f);
            uint32_t tb = tf32r(t);
            Tb[idx] = tb;
            Zb[idx] = tb;
        }
    }
    __syncthreads();

    // ---- iter 1 (reduced): Y = Y @ T1, triangular ----
    {
        float acc[2][4][4];
        zero4(acc[0]); zero4(acc[1]);
        if (pbig)       mm32(Yb, Tb, acc, P1r, P1c, lane);
        else if (p1act) mm16(Yb, Tb, acc[0], P1r, P1c, lane);
        __syncthreads();
        if (p1act) {
            epi_t(acc[0], Yb, 1.f, 0.f, P1r, P1c, lane, P1m);
            if (pbig) epi_t(acc[1], Yb, 1.f, 0.f, P1r + 16, P1c, lane, P1m);
        }
        __syncthreads();
    }

    // ---- iters 2..5 ----
#pragma unroll 1
    for (int it = 1; it < 5; ++it) {
        // P1: T = 1.5I - 0.5*(Z @ Y); epilogue fused (T not a P1 operand)
        {
            float acc[2][4][4];
            zero4(acc[0]); zero4(acc[1]);
            if (pbig) {
                mm32(Zb, Yb, acc, P1r, P1c, lane);
                epi_t(acc[0], Tb, -0.5f, 1.5f, P1r, P1c, lane, P1m);
                epi_t(acc[1], Tb, -0.5f, 1.5f, P1r + 16, P1c, lane, P1m);
            } else if (p1act) {
                mm16(Zb, Yb, acc[0], P1r, P1c, lane);
                epi_t(acc[0], Tb, -0.5f, 1.5f, P1r, P1c, lane, P1m);
            }
        }
        __syncthreads();

        if (it < 4) {
            // P2: Y = Y@T / Z = Z@T via m64 panels + m32 tails
            float acc[4][4][4];
            if (p2m64) {
                zero4(acc[0]); zero4(acc[1]); zero4(acc[2]); zero4(acc[3]);
                mm64(p2z ? Zb : Yb, Tb, acc, P2r, P2c, lane);
            } else if (p2m32) {
                zero4(acc[0]); zero4(acc[1]);
                mm32(p2z ? Zb : Yb, Tb, (float(*)[4][4])acc, P2r, P2c, lane);
            }
            __syncthreads();
            uint32_t* D = p2z ? Zb : Yb;
            if (p2m64) {
#pragma unroll
                for (int g = 0; g < 4; g++) {
                    const int rg = P2r + g * 16;
                    epi_t(acc[g], D, 1.f, 0.f, rg, P2c, lane,
                          (rg >> 5) != (P2c >> 5));
                }
            } else if (p2m32) {
#pragma unroll
                for (int g = 0; g < 2; g++) {
                    const int rg = P2r + g * 16;
                    epi_t(acc[g], D, 1.f, 0.f, rg, P2c, lane,
                          (rg >> 5) != (P2c >> 5));
                }
            }
            __syncthreads();
        } else {
            // Last: Y5 = Y@T full grid (16 m32 tiles), straight to GMEM
            const float s = sqrtf(normA);
            float acc[2][4][4];
            zero4(acc[0]); zero4(acc[1]);
            mm32(Yb, Tb, acc, Lr, Lc, lane);
            epi_out(acc[0], Ob, s, Lr, Lc, lane);
            epi_out(acc[1], Ob, s, Lr + 16, Lc, lane);
        }
    }
}

extern "C" void kernel_launch(void* const* d_in, const int* in_sizes, int n_in,
                              void* d_out, int out_size) {
    const float* A = (const float*)d_in[0];
    float* out = (float*)d_out;
    const int nbatch = in_sizes[0] / (NMAT * NMAT);           // 1024
    const size_t smem = 3 * 128 * PITCHW * sizeof(uint32_t);  // 202752 B
    cudaFuncSetAttribute(ns_tf32_kernel,
                         cudaFuncAttributeMaxDynamicSharedMemorySize, (int)smem);
    ns_tf32_kernel<<<nbatch, NT, smem>>>(A, out);
}

// round 15
// speedup vs baseline: 1.9049x; 1.5781x over previous
#include <cuda_runtime.h>
#include <cuda_fp16.h>
#include <cstdint>

// Batched Newton-Schulz matrix sqrt: 1024 x (128x128 fp32), 5 iterations.
// Single-pass FP16 mma.sync (m16n8k16, fp32 accum). fp16 mantissa (11 bit)
// == tf32 granularity, but half the MMA instructions and half the smem
// bytes of the tf32 version. Triangular outputs + mirror (symmetry).
// P1: m32 tiles; P2: m64n32 column panels; last iter: m32 full grid.

#define NMAT 128
#define NT 512
#define PITCH32 68      // u32 words per smem row
#define PITCHB 272      // bytes per smem row (conflict-free)
#define PITCH16 136

__device__ __forceinline__ void mma_f16(float* d, const uint32_t* a,
                                        const uint32_t* b) {
    asm volatile(
        "mma.sync.aligned.m16n8k16.row.col.f32.f16.f16.f32 "
        "{%0,%1,%2,%3}, {%4,%5,%6,%7}, {%8,%9}, {%0,%1,%2,%3};"
        : "+f"(d[0]), "+f"(d[1]), "+f"(d[2]), "+f"(d[3])
        : "r"(a[0]), "r"(a[1]), "r"(a[2]), "r"(a[3]), "r"(b[0]), "r"(b[1]));
}

#define LDSM4(r_, a_)                                                         \
    asm volatile("ldmatrix.sync.aligned.m8n8.x4.shared.b16 {%0,%1,%2,%3}, [%4];" \
                 : "=r"((r_)[0]), "=r"((r_)[1]), "=r"((r_)[2]), "=r"((r_)[3])  \
                 : "r"(a_))

__device__ __forceinline__ uint32_t sp(const void* p) {
    return (uint32_t)__cvta_generic_to_shared(p);
}

__device__ __forceinline__ uint32_t h2pack(float v0, float v1) {
    uint32_t r;
    asm("cvt.rn.f16x2.f32 %0, %1, %2;" : "=r"(r) : "f"(v1), "f"(v0));
    return r;
}

__device__ __forceinline__ void zero4(float a[4][4]) {
#pragma unroll
    for (int i = 0; i < 4; i++)
#pragma unroll
        for (int j = 0; j < 4; j++) a[i][j] = 0.f;
}

// ldmatrix octet addressing (16-bit rows)
__device__ __forceinline__ uint32_t a_off(int r0, int lane) {
    return (uint32_t)((r0 + (lane & 7) + ((lane >> 3) & 1) * 8) * PITCHB +
                      (lane >> 4) * 16);
}
__device__ __forceinline__ uint32_t b_off(int c0, int lane) {
    return (uint32_t)((c0 + (lane & 7) + (lane >> 4) * 8) * PITCHB +
                      ((lane >> 3) & 1) * 16);
}

// m16n32: acc[4][4]
__device__ __forceinline__ void mm16(const uint32_t* P, const uint32_t* Q,
                                     float acc[4][4], int r0, int c0, int lane) {
    const uint32_t pa = sp(P) + a_off(r0, lane);
    uint32_t qb0 = sp(Q) + b_off(c0, lane);
    uint32_t qb1 = qb0 + 16 * PITCHB;
#pragma unroll
    for (int k = 0; k < 8; k++) {
        uint32_t a[4], b[8];
        LDSM4(a, pa + k * 32);
        LDSM4(b, qb0); LDSM4(b + 4, qb1);
        qb0 += 32; qb1 += 32;
#pragma unroll
        for (int ni = 0; ni < 4; ni++) mma_f16(acc[ni], a, b + ni * 2);
    }
}

// m32n32: acc[2][4][4]
__device__ __forceinline__ void mm32(const uint32_t* P, const uint32_t* Q,
                                     float acc[2][4][4], int r0, int c0,
                                     int lane) {
    const uint32_t pa0 = sp(P) + a_off(r0, lane);
    const uint32_t pa1 = sp(P) + a_off(r0 + 16, lane);
    uint32_t qb0 = sp(Q) + b_off(c0, lane);
    uint32_t qb1 = qb0 + 16 * PITCHB;
#pragma unroll
    for (int k = 0; k < 8; k++) {
        uint32_t a0[4], a1[4], b[8];
        LDSM4(a0, pa0 + k * 32);
        LDSM4(a1, pa1 + k * 32);
        LDSM4(b, qb0); LDSM4(b + 4, qb1);
        qb0 += 32; qb1 += 32;
#pragma unroll
        for (int ni = 0; ni < 4; ni++) {
            mma_f16(acc[0][ni], a0, b + ni * 2);
            mma_f16(acc[1][ni], a1, b + ni * 2);
        }
    }
}

// m64n32: acc[4][4][4]; B resident per k-step, A streamed per row-group
__device__ __forceinline__ void mm64(const uint32_t* P, const uint32_t* Q,
                                     float acc[4][4][4], int r0, int c0,
                                     int lane) {
    const uint32_t pa = sp(P) + a_off(r0, lane);
    uint32_t qb0 = sp(Q) + b_off(c0, lane);
    uint32_t qb1 = qb0 + 16 * PITCHB;
#pragma unroll
    for (int k = 0; k < 8; k++) {
        uint32_t b[8];
        LDSM4(b, qb0); LDSM4(b + 4, qb1);
        qb0 += 32; qb1 += 32;
#pragma unroll
        for (int mi = 0; mi < 4; mi++) {
            uint32_t a[4];
            LDSM4(a, pa + (uint32_t)(mi * 16 * PITCHB + k * 32));
#pragma unroll
            for (int ni = 0; ni < 4; ni++) mma_f16(acc[mi][ni], a, b + ni * 2);
        }
    }
}

// v = alpha*acc + beta*I -> fp16 words; optional mirror to transposed pos.
__device__ __forceinline__ void epi_t(const float acc[4][4],
                                      uint32_t* __restrict__ B, float alpha,
                                      float beta, int r0, int c0, int lane,
                                      bool mir) {
    const int qr = lane >> 2, cp = (lane & 3) * 2;
    uint16_t* B16 = (uint16_t*)B;
#pragma unroll
    for (int ni = 0; ni < 4; ni++) {
        const int col = c0 + ni * 8 + cp;
#pragma unroll
        for (int h = 0; h < 2; h++) {
            const int row = r0 + qr + h * 8;
            float v0 = alpha * acc[ni][2 * h]     + ((row == col)     ? beta : 0.f);
            float v1 = alpha * acc[ni][2 * h + 1] + ((row == col + 1) ? beta : 0.f);
            uint32_t hw = h2pack(v0, v1);
            B[row * PITCH32 + (col >> 1)] = hw;
            if (mir) {
                B16[col * PITCH16 + row]       = (uint16_t)hw;
                B16[(col + 1) * PITCH16 + row] = (uint16_t)(hw >> 16);
            }
        }
    }
}

__device__ __forceinline__ void epi_out(const float acc[4][4],
                                        float* __restrict__ Ob, float s,
                                        int r0, int c0, int lane) {
    const int qr = lane >> 2, cp = (lane & 3) * 2;
#pragma unroll
    for (int ni = 0; ni < 4; ni++) {
        const int col = c0 + ni * 8 + cp;
#pragma unroll
        for (int h = 0; h < 2; h++) {
            const int row = r0 + qr + h * 8;
            *(float2*)(Ob + row * 128 + col) =
                make_float2(s * acc[ni][2 * h], s * acc[ni][2 * h + 1]);
        }
    }
}

__device__ __constant__ int LTI[10] = {0, 1, 1, 2, 2, 2, 3, 3, 3, 3};
__device__ __constant__ int LTJ[10] = {0, 0, 1, 0, 1, 2, 0, 1, 2, 3};
// P2 m64 column-panels of the lower triangle
__device__ __constant__ int P64R[4] = {0, 64, 32, 64};
__device__ __constant__ int P64C[4] = {0, 0, 32, 64};

__global__ void __launch_bounds__(NT, 1)
ns_f16_kernel(const float* __restrict__ A, float* __restrict__ Out) {
    extern __shared__ uint32_t sm[];
    uint32_t* Yb = sm;
    uint32_t* Zb = sm + 128 * PITCH32;
    uint32_t* Tb = sm + 2 * 128 * PITCH32;
    __shared__ float red[16];

    const int tid = threadIdx.x, w = tid >> 5, lane = tid & 31;
    const float* Ab = A + (size_t)blockIdx.x * 16384;
    float* Ob = Out + (size_t)blockIdx.x * 16384;

    // --- P1: warps 0-7 m32 tiles 0-7; warps 8-11 m16 halves of tiles 8,9 ---
    const bool pbig = (w < 8);
    const bool p1act = (w < 12);
    const int p1t = pbig ? w : (8 + ((w - 8) >> 1));
    const int P1r = LTI[p1t] * 32 + (pbig ? 0 : ((w - 8) & 1) * 16);
    const int P1c = LTJ[p1t] * 32;
    const bool P1m = (LTI[p1t] != LTJ[p1t]);
    // --- P2: 8 m64 panels (warps 0-7) + 4 m32 panels (warps 8-11) ---
    const bool p2m64 = (w < 8);
    const bool p2m32 = (w >= 8) && (w < 12);
    const bool p2z = p2m64 ? (w >= 4) : (w >= 10);
    const int p2i = w & 3;
    const int P2r = p2m64 ? P64R[p2i] : 96;
    const int P2c = p2m64 ? P64C[p2i] : ((w & 1) ? 96 : 32);
    // --- last iter: 16 m32 tiles ---
    const int Lr = (w & 3) * 32, Lc = (w >> 2) * 32;

    // ---- Frobenius norm ----
    float ss = 0.f;
    const float4* A4 = (const float4*)Ab;
    for (int i = tid; i < 4096; i += NT) {
        float4 v = A4[i];
        ss = fmaf(v.x, v.x, fmaf(v.y, v.y, fmaf(v.z, v.z, fmaf(v.w, v.w, ss))));
    }
#pragma unroll
    for (int o = 16; o; o >>= 1) ss += __shfl_xor_sync(0xffffffffu, ss, o);
    if (lane == 0) red[w] = ss;
    __syncthreads();
    float tot = 0.f;
#pragma unroll
    for (int i = 0; i < 16; i++) tot += red[i];
    const float normA = sqrtf(tot);
    const float inv = 1.f / normA;

    // ---- Init: Y0 = f16(A*inv); T1 = Z1 = f16(1.5I - 0.5*Y0) ----
    for (int u = tid; u < 2048; u += NT) {
        const int row = u >> 4;
        const int col = (u & 15) * 8;
        float4 a0 = *(const float4*)(Ab + row * 128 + col);
        float4 a1 = *(const float4*)(Ab + row * 128 + col + 4);
        float yv[8] = {a0.x * inv, a0.y * inv, a0.z * inv, a0.w * inv,
                       a1.x * inv, a1.y * inv, a1.z * inv, a1.w * inv};
#pragma unroll
        for (int jj = 0; jj < 4; jj++) {
            const int cc = col + 2 * jj;
            const int idx = row * PITCH32 + (cc >> 1);
            Yb[idx] = h2pack(yv[2 * jj], yv[2 * jj + 1]);
            float t0 = -0.5f * yv[2 * jj]     + (row == cc     ? 1.5f : 0.f);
            float t1 = -0.5f * yv[2 * jj + 1] + (row == cc + 1 ? 1.5f : 0.f);
            uint32_t tb = h2pack(t0, t1);
            Tb[idx] = tb;
            Zb[idx] = tb;
        }
    }
    __syncthreads();

    // ---- iter 1 (reduced): Y = Y @ T1, triangular ----
    {
        float acc[2][4][4];
        zero4(acc[0]); zero4(acc[1]);
        if (pbig)       mm32(Yb, Tb, acc, P1r, P1c, lane);
        else if (p1act) mm16(Yb, Tb, acc[0], P1r, P1c, lane);
        __syncthreads();
        if (p1act) {
            epi_t(acc[0], Yb, 1.f, 0.f, P1r, P1c, lane, P1m);
            if (pbig) epi_t(acc[1], Yb, 1.f, 0.f, P1r + 16, P1c, lane, P1m);
        }
        __syncthreads();
    }

    // ---- iters 2..5 ----
#pragma unroll 1
    for (int it = 1; it < 5; ++it) {
        // P1: T = 1.5I - 0.5*(Z @ Y); epilogue fused (T not a P1 operand)
        {
            float acc[2][4][4];
            zero4(acc[0]); zero4(acc[1]);
            if (pbig) {
                mm32(Zb, Yb, acc, P1r, P1c, lane);
                epi_t(acc[0], Tb, -0.5f, 1.5f, P1r, P1c, lane, P1m);
                epi_t(acc[1], Tb, -0.5f, 1.5f, P1r + 16, P1c, lane, P1m);
            } else if (p1act) {
                mm16(Zb, Yb, acc[0], P1r, P1c, lane);
                epi_t(acc[0], Tb, -0.5f, 1.5f, P1r, P1c, lane, P1m);
            }
        }
        __syncthreads();

        if (it < 4) {
            // P2: Y = Y@T / Z = Z@T via m64 panels + m32 tails
            float acc[4][4][4];
            if (p2m64) {
                zero4(acc[0]); zero4(acc[1]); zero4(acc[2]); zero4(acc[3]);
                mm64(p2z ? Zb : Yb, Tb, acc, P2r, P2c, lane);
            } else if (p2m32) {
                zero4(acc[0]); zero4(acc[1]);
                mm32(p2z ? Zb : Yb, Tb, (float(*)[4][4])acc, P2r, P2c, lane);
            }
            __syncthreads();
            uint32_t* D = p2z ? Zb : Yb;
            if (p2m64) {
#pragma unroll
                for (int g = 0; g < 4; g++) {
                    const int rg = P2r + g * 16;
                    epi_t(acc[g], D, 1.f, 0.f, rg, P2c, lane,
                          (rg >> 5) != (P2c >> 5));
                }
            } else if (p2m32) {
#pragma unroll
                for (int g = 0; g < 2; g++) {
                    const int rg = P2r + g * 16;
                    epi_t(acc[g], D, 1.f, 0.f, rg, P2c, lane,
                          (rg >> 5) != (P2c >> 5));
                }
            }
            __syncthreads();
        } else {
            // Last: Y5 = Y@T full grid (16 m32 tiles), straight to GMEM
            const float s = sqrtf(normA);
            float acc[2][4][4];
            zero4(acc[0]); zero4(acc[1]);
            mm32(Yb, Tb, acc, Lr, Lc, lane);
            epi_out(acc[0], Ob, s, Lr, Lc, lane);
            epi_out(acc[1], Ob, s, Lr + 16, Lc, lane);
        }
    }
}

extern "C" void kernel_launch(void* const* d_in, const int* in_sizes, int n_in,
                              void* d_out, int out_size) {
    const float* A = (const float*)d_in[0];
    float* out = (float*)d_out;
    const int nbatch = in_sizes[0] / (NMAT * NMAT);           // 1024
    const size_t smem = 3 * 128 * PITCH32 * sizeof(uint32_t); // 104448 B
    cudaFuncSetAttribute(ns_f16_kernel,
                         cudaFuncAttributeMaxDynamicSharedMemorySize, (int)smem);
    ns_f16_kernel<<<nbatch, NT, smem>>>(A, out);
}

// round 16
// speedup vs baseline: 2.2332x; 1.1724x over previous
#include <cuda_runtime.h>
#include <cuda_fp16.h>
#include <cstdint>

// Batched Newton-Schulz matrix sqrt: 1024 x (128x128 fp32), 5 iterations.
// FP16 mma.sync (m16n8k16, fp32 accum), triangular outputs + mirror.
// 256-thread CTAs with 2 CTAs/SM (104KB smem each, 128-reg cap): one CTA's
// epilogue/barrier stalls hide under the other's MMA phase.

#define NMAT 128
#define NT 256
#define PITCH32 68      // u32 words per smem row
#define PITCHB 272      // bytes per smem row (conflict-free)
#define PITCH16 136

__device__ __forceinline__ void mma_f16(float* d, const uint32_t* a,
                                        const uint32_t* b) {
    asm volatile(
        "mma.sync.aligned.m16n8k16.row.col.f32.f16.f16.f32 "
        "{%0,%1,%2,%3}, {%4,%5,%6,%7}, {%8,%9}, {%0,%1,%2,%3};"
        : "+f"(d[0]), "+f"(d[1]), "+f"(d[2]), "+f"(d[3])
        : "r"(a[0]), "r"(a[1]), "r"(a[2]), "r"(a[3]), "r"(b[0]), "r"(b[1]));
}

#define LDSM4(r_, a_)                                                         \
    asm volatile("ldmatrix.sync.aligned.m8n8.x4.shared.b16 {%0,%1,%2,%3}, [%4];" \
                 : "=r"((r_)[0]), "=r"((r_)[1]), "=r"((r_)[2]), "=r"((r_)[3])  \
                 : "r"(a_))

__device__ __forceinline__ uint32_t sp(const void* p) {
    return (uint32_t)__cvta_generic_to_shared(p);
}

__device__ __forceinline__ uint32_t h2pack(float v0, float v1) {
    uint32_t r;
    asm("cvt.rn.f16x2.f32 %0, %1, %2;" : "=r"(r) : "f"(v1), "f"(v0));
    return r;
}

__device__ __forceinline__ void zero4(float a[4][4]) {
#pragma unroll
    for (int i = 0; i < 4; i++)
#pragma unroll
        for (int j = 0; j < 4; j++) a[i][j] = 0.f;
}

// ldmatrix octet addressing (16-bit rows)
__device__ __forceinline__ uint32_t a_off(int r0, int lane) {
    return (uint32_t)((r0 + (lane & 7) + ((lane >> 3) & 1) * 8) * PITCHB +
                      (lane >> 4) * 16);
}
__device__ __forceinline__ uint32_t b_off(int c0, int lane) {
    return (uint32_t)((c0 + (lane & 7) + (lane >> 4) * 8) * PITCHB +
                      ((lane >> 3) & 1) * 16);
}

// m16n32: acc[4][4]
__device__ __forceinline__ void mm16(const uint32_t* P, const uint32_t* Q,
                                     float acc[4][4], int r0, int c0, int lane) {
    const uint32_t pa = sp(P) + a_off(r0, lane);
    uint32_t qb0 = sp(Q) + b_off(c0, lane);
    uint32_t qb1 = qb0 + 16 * PITCHB;
#pragma unroll
    for (int k = 0; k < 8; k++) {
        uint32_t a[4], b[8];
        LDSM4(a, pa + k * 32);
        LDSM4(b, qb0); LDSM4(b + 4, qb1);
        qb0 += 32; qb1 += 32;
#pragma unroll
        for (int ni = 0; ni < 4; ni++) mma_f16(acc[ni], a, b + ni * 2);
    }
}

// m32n32: acc[2][4][4] (B shared across both row groups)
__device__ __forceinline__ void mm32(const uint32_t* P, const uint32_t* Q,
                                     float acc[2][4][4], int r0, int c0,
                                     int lane) {
    const uint32_t pa0 = sp(P) + a_off(r0, lane);
    const uint32_t pa1 = sp(P) + a_off(r0 + 16, lane);
    uint32_t qb0 = sp(Q) + b_off(c0, lane);
    uint32_t qb1 = qb0 + 16 * PITCHB;
#pragma unroll
    for (int k = 0; k < 8; k++) {
        uint32_t a0[4], a1[4], b[8];
        LDSM4(a0, pa0 + k * 32);
        LDSM4(a1, pa1 + k * 32);
        LDSM4(b, qb0); LDSM4(b + 4, qb1);
        qb0 += 32; qb1 += 32;
#pragma unroll
        for (int ni = 0; ni < 4; ni++) {
            mma_f16(acc[0][ni], a0, b + ni * 2);
            mma_f16(acc[1][ni], a1, b + ni * 2);
        }
    }
}

// v = alpha*acc + beta*I -> fp16 words; optional mirror to transposed pos.
__device__ __forceinline__ void epi_t(const float acc[4][4],
                                      uint32_t* __restrict__ B, float alpha,
                                      float beta, int r0, int c0, int lane,
                                      bool mir) {
    const int qr = lane >> 2, cp = (lane & 3) * 2;
    uint16_t* B16 = (uint16_t*)B;
#pragma unroll
    for (int ni = 0; ni < 4; ni++) {
        const int col = c0 + ni * 8 + cp;
#pragma unroll
        for (int h = 0; h < 2; h++) {
            const int row = r0 + qr + h * 8;
            float v0 = alpha * acc[ni][2 * h]     + ((row == col)     ? beta : 0.f);
            float v1 = alpha * acc[ni][2 * h + 1] + ((row == col + 1) ? beta : 0.f);
            uint32_t hw = h2pack(v0, v1);
            B[row * PITCH32 + (col >> 1)] = hw;
            if (mir) {
                B16[col * PITCH16 + row]       = (uint16_t)hw;
                B16[(col + 1) * PITCH16 + row] = (uint16_t)(hw >> 16);
            }
        }
    }
}

__device__ __forceinline__ void epi_out(const float acc[4][4],
                                        float* __restrict__ Ob, float s,
                                        int r0, int c0, int lane) {
    const int qr = lane >> 2, cp = (lane & 3) * 2;
#pragma unroll
    for (int ni = 0; ni < 4; ni++) {
        const int col = c0 + ni * 8 + cp;
#pragma unroll
        for (int h = 0; h < 2; h++) {
            const int row = r0 + qr + h * 8;
            *(float2*)(Ob + row * 128 + col) =
                make_float2(s * acc[ni][2 * h], s * acc[ni][2 * h + 1]);
        }
    }
}

__device__ __constant__ int LTI[10] = {0, 1, 1, 2, 2, 2, 3, 3, 3, 3};
__device__ __constant__ int LTJ[10] = {0, 0, 1, 0, 1, 2, 0, 1, 2, 3};

__global__ void __launch_bounds__(NT, 2)
ns_occ2_kernel(const float* __restrict__ A, float* __restrict__ Out) {
    extern __shared__ uint32_t sm[];
    uint32_t* Yb = sm;
    uint32_t* Zb = sm + 128 * PITCH32;
    uint32_t* Tb = sm + 2 * 128 * PITCH32;
    __shared__ float red[8];

    const int tid = threadIdx.x, w = tid >> 5, lane = tid & 31;
    const float* Ab = A + (size_t)blockIdx.x * 16384;
    float* Ob = Out + (size_t)blockIdx.x * 16384;

    // --- P1 geometry (8 warps): m32 tile w; warps 0-3 extra m16 half of
    // tiles 8 ((3,2), mirror) / 9 ((3,3), diag) ---
    const int P1r = LTI[w] * 32, P1c = LTJ[w] * 32;
    const bool P1m = (LTI[w] != LTJ[w]);
    const bool p1x = (w < 4);
    const int p1xp = 8 + (w >> 1);
    const int P1xr = LTI[p1xp] * 32 + (w & 1) * 16;
    const int P1xc = LTJ[p1xp] * 32;
    const bool P1xm = (LTI[p1xp] != LTJ[p1xp]);
    // --- P2: warp w owns m32 tasks 2w, 2w+1 of [Y tiles 0-9, Z tiles 0-5],
    // plus m16 half (w&1) of Z tile 6+(w>>1) ---
    const int tA = 2 * w, tB = 2 * w + 1;
    const bool zA = (tA >= 10), zB = (tB >= 10);
    const int tiA = zA ? tA - 10 : tA, tiB = zB ? tB - 10 : tB;
    const int P2ar = LTI[tiA] * 32, P2ac = LTJ[tiA] * 32;
    const int P2br = LTI[tiB] * 32, P2bc = LTJ[tiB] * 32;
    const bool P2am = (LTI[tiA] != LTJ[tiA]);
    const bool P2bm = (LTI[tiB] != LTJ[tiB]);
    const int p2cp = 6 + (w >> 1);
    const int P2cr = LTI[p2cp] * 32 + (w & 1) * 16;
    const int P2cc = LTJ[p2cp] * 32;
    const bool P2cm = (LTI[p2cp] != LTJ[p2cp]);
    // --- last iter: m32 tiles w and w+8 of the full 4x4 grid ---
    const int LAr = (w & 3) * 32, LAc = (w >> 2) * 32;
    const int LBr = ((w + 8) & 3) * 32, LBc = ((w + 8) >> 2) * 32;

    // ---- Frobenius norm ----
    float ss = 0.f;
    const float4* A4 = (const float4*)Ab;
    for (int i = tid; i < 4096; i += NT) {
        float4 v = A4[i];
        ss = fmaf(v.x, v.x, fmaf(v.y, v.y, fmaf(v.z, v.z, fmaf(v.w, v.w, ss))));
    }
#pragma unroll
    for (int o = 16; o; o >>= 1) ss += __shfl_xor_sync(0xffffffffu, ss, o);
    if (lane == 0) red[w] = ss;
    __syncthreads();
    float tot = 0.f;
#pragma unroll
    for (int i = 0; i < 8; i++) tot += red[i];
    const float normA = sqrtf(tot);
    const float inv = 1.f / normA;

    // ---- Init: Y0 = f16(A*inv); T1 = Z1 = f16(1.5I - 0.5*Y0) ----
    for (int u = tid; u < 2048; u += NT) {
        const int row = u >> 4;
        const int col = (u & 15) * 8;
        float4 a0 = *(const float4*)(Ab + row * 128 + col);
        float4 a1 = *(const float4*)(Ab + row * 128 + col + 4);
        float yv[8] = {a0.x * inv, a0.y * inv, a0.z * inv, a0.w * inv,
                       a1.x * inv, a1.y * inv, a1.z * inv, a1.w * inv};
#pragma unroll
        for (int jj = 0; jj < 4; jj++) {
            const int cc = col + 2 * jj;
            const int idx = row * PITCH32 + (cc >> 1);
            Yb[idx] = h2pack(yv[2 * jj], yv[2 * jj + 1]);
            float t0 = -0.5f * yv[2 * jj]     + (row == cc     ? 1.5f : 0.f);
            float t1 = -0.5f * yv[2 * jj + 1] + (row == cc + 1 ? 1.5f : 0.f);
            uint32_t tb = h2pack(t0, t1);
            Tb[idx] = tb;
            Zb[idx] = tb;
        }
    }
    __syncthreads();

    // ---- iter 1 (reduced): Y = Y @ T1, triangular ----
    {
        float acc[2][4][4], accx[4][4];
        zero4(acc[0]); zero4(acc[1]);
        mm32(Yb, Tb, acc, P1r, P1c, lane);
        if (p1x) {
            zero4(accx);
            mm16(Yb, Tb, accx, P1xr, P1xc, lane);
        }
        __syncthreads();
        epi_t(acc[0], Yb, 1.f, 0.f, P1r, P1c, lane, P1m);
        epi_t(acc[1], Yb, 1.f, 0.f, P1r + 16, P1c, lane, P1m);
        if (p1x) epi_t(accx, Yb, 1.f, 0.f, P1xr, P1xc, lane, P1xm);
        __syncthreads();
    }

    // ---- iters 2..5 ----
#pragma unroll 1
    for (int it = 1; it < 5; ++it) {
        // P1: T = 1.5I - 0.5*(Z @ Y); epilogue fused (T not a P1 operand)
        {
            float acc[2][4][4];
            zero4(acc[0]); zero4(acc[1]);
            mm32(Zb, Yb, acc, P1r, P1c, lane);
            epi_t(acc[0], Tb, -0.5f, 1.5f, P1r, P1c, lane, P1m);
            epi_t(acc[1], Tb, -0.5f, 1.5f, P1r + 16, P1c, lane, P1m);
            if (p1x) {
                float accx[4][4];
                zero4(accx);
                mm16(Zb, Yb, accx, P1xr, P1xc, lane);
                epi_t(accx, Tb, -0.5f, 1.5f, P1xr, P1xc, lane, P1xm);
            }
        }
        __syncthreads();

        if (it < 4) {
            // P2: per warp 2 m32 tasks + 1 m16 tail (Y@T / Z@T)
            float accA[2][4][4], accB[2][4][4], accC[4][4];
            zero4(accA[0]); zero4(accA[1]);
            mm32(zA ? Zb : Yb, Tb, accA, P2ar, P2ac, lane);
            zero4(accB[0]); zero4(accB[1]);
            mm32(zB ? Zb : Yb, Tb, accB, P2br, P2bc, lane);
            zero4(accC);
            mm16(Zb, Tb, accC, P2cr, P2cc, lane);
            __syncthreads();
            {
                uint32_t* DA = zA ? Zb : Yb;
                epi_t(accA[0], DA, 1.f, 0.f, P2ar, P2ac, lane, P2am);
                epi_t(accA[1], DA, 1.f, 0.f, P2ar + 16, P2ac, lane, P2am);
                uint32_t* DB = zB ? Zb : Yb;
                epi_t(accB[0], DB, 1.f, 0.f, P2br, P2bc, lane, P2bm);
                epi_t(accB[1], DB, 1.f, 0.f, P2br + 16, P2bc, lane, P2bm);
                epi_t(accC, Zb, 1.f, 0.f, P2cr, P2cc, lane, P2cm);
            }
            __syncthreads();
        } else {
            // Last: Y5 = Y@T full grid (2 m32 tiles/warp), straight to GMEM
            const float s = sqrtf(normA);
            float acc[2][4][4];
            zero4(acc[0]); zero4(acc[1]);
            mm32(Yb, Tb, acc, LAr, LAc, lane);
            epi_out(acc[0], Ob, s, LAr, LAc, lane);
            epi_out(acc[1], Ob, s, LAr + 16, LAc, lane);
            zero4(acc[0]); zero4(acc[1]);
            mm32(Yb, Tb, acc, LBr, LBc, lane);
            epi_out(acc[0], Ob, s, LBr, LBc, lane);
            epi_out(acc[1], Ob, s, LBr + 16, LBc, lane);
        }
    }
}

extern "C" void kernel_launch(void* const* d_in, const int* in_sizes, int n_in,
                              void* d_out, int out_size) {
    const float* A = (const float*)d_in[0];
    float* out = (float*)d_out;
    const int nbatch = in_sizes[0] / (NMAT * NMAT);           // 1024
    const size_t smem = 3 * 128 * PITCH32 * sizeof(uint32_t); // 104448 B
    cudaFuncSetAttribute(ns_occ2_kernel,
                         cudaFuncAttributeMaxDynamicSharedMemorySize, (int)smem);
    ns_occ2_kernel<<<nbatch, NT, smem>>>(A, out);
}